// round 1
// baseline (speedup 1.0000x reference)
#include <cuda_runtime.h>
#include <cstdint>

#define UNITS 20
#define KDIM  40          // 2*UNITS (x then h)
#define GATES 80          // 4*UNITS, order: i, f, g, o
#define TPB   128

typedef unsigned long long ull;

// ---- packed f32x2 helpers (FFMA2 only reachable via PTX) ----
__device__ __forceinline__ ull splat2(float x){
    ull r; asm("mov.b64 %0, {%1, %1};" : "=l"(r) : "f"(x)); return r;
}
__device__ __forceinline__ ull fma2(ull a, ull b, ull c){
    ull d; asm("fma.rn.f32x2 %0, %1, %2, %3;" : "=l"(d) : "l"(a), "l"(b), "l"(c)); return d;
}
__device__ __forceinline__ void unpack2(ull p, float &lo, float &hi){
    asm("mov.b64 {%0, %1}, %2;" : "=f"(lo), "=f"(hi) : "l"(p));
}

// ---- fast transcendentals (ex2/rcp approx: ~1-2 ulp, far under 1e-3 budget) ----
__device__ __forceinline__ float fast_ex2(float x){
    float y; asm("ex2.approx.f32 %0, %1;" : "=f"(y) : "f"(x)); return y;
}
__device__ __forceinline__ float fast_rcp(float x){
    float y; asm("rcp.approx.f32 %0, %1;" : "=f"(y) : "f"(x)); return y;
}
__device__ __forceinline__ float fsigmoid(float x){
    // 1/(1+e^-x); handles +-inf limits correctly via ex2->{0,inf}, rcp(inf)=0
    float e = fast_ex2(-1.4426950408889634f * x);
    return fast_rcp(1.0f + e);
}
__device__ __forceinline__ float ftanh(float x){
    // tanh(x) = 1 - 2/(e^{2x}+1)
    float e = fast_ex2(2.8853900817779268f * x);
    float r = fast_rcp(e + 1.0f);
    return fmaf(-2.0f, r, 1.0f);
}

__global__ void __launch_bounds__(TPB, 3)
stn_gpe_kernel(const float* __restrict__ x, const float* __restrict__ h,
               const float* __restrict__ c,
               const float* __restrict__ W_ih, const float* __restrict__ W_hh,
               const float* __restrict__ b_ih, const float* __restrict__ b_hh,
               const float* __restrict__ W_lat,
               float* __restrict__ out, int nrows)
{
    // weights transposed+combined: w_s[k*80 + j] = W[j][k] for k<20 from W_ih, else W_hh
    __shared__ __align__(16) float w_s[KDIM * GATES];          // 12800 B
    __shared__ __align__(16) float b_s[GATES];                 // b_ih + b_hh
    __shared__ __align__(16) float wl_s[UNITS * UNITS];        // wl_s[v*20+u] = W_lat[u][v]
    __shared__ __align__(16) float in_s[TPB * 41];             // per-thread x(20),h(20), pad 41

    const int tid = threadIdx.x;

    // ---- fill shared weights ----
    for (int idx = tid; idx < KDIM * GATES; idx += TPB){
        int k = idx / GATES, j = idx - k * GATES;
        w_s[idx] = (k < UNITS) ? W_ih[j * UNITS + k] : W_hh[j * UNITS + (k - UNITS)];
    }
    for (int idx = tid; idx < GATES; idx += TPB) b_s[idx] = b_ih[idx] + b_hh[idx];
    for (int idx = tid; idx < UNITS * UNITS; idx += TPB){
        int v = idx / UNITS, u = idx - v * UNITS;
        wl_s[idx] = W_lat[u * UNITS + v];
    }

    const long r = (long)blockIdx.x * TPB + tid;
    const bool active = (r < (long)nrows);

    // ---- stage this thread's inputs into smem (coalesced float4 gmem loads) ----
    if (active){
        const float4* xp = (const float4*)(x + r * 20);
        const float4* hp = (const float4*)(h + r * 20);
        #pragma unroll
        for (int i = 0; i < 5; i++){
            float4 v = xp[i];
            in_s[tid * 41 + 4*i + 0] = v.x;
            in_s[tid * 41 + 4*i + 1] = v.y;
            in_s[tid * 41 + 4*i + 2] = v.z;
            in_s[tid * 41 + 4*i + 3] = v.w;
            float4 w = hp[i];
            in_s[tid * 41 + 20 + 4*i + 0] = w.x;
            in_s[tid * 41 + 20 + 4*i + 1] = w.y;
            in_s[tid * 41 + 20 + 4*i + 2] = w.z;
            in_s[tid * 41 + 20 + 4*i + 3] = w.w;
        }
    }
    __syncthreads();

    // ---- gate GEMV: 80 gates as 40 packed f32x2 accumulators ----
    ull acc[40];
    {
        const ull* b2 = (const ull*)b_s;
        #pragma unroll
        for (int j2 = 0; j2 < 40; j2++) acc[j2] = b2[j2];
    }
    const ull* w2 = (const ull*)w_s;
    #pragma unroll 2
    for (int k = 0; k < KDIM; k++){
        ull s = splat2(in_s[tid * 41 + k]);
        const ull* wr = w2 + k * 40;
        #pragma unroll
        for (int j2 = 0; j2 < 40; j2++) acc[j2] = fma2(s, wr[j2], acc[j2]);
    }

    // ---- unpack gates ----
    float g[GATES];
    #pragma unroll
    for (int j2 = 0; j2 < 40; j2++) unpack2(acc[j2], g[2*j2], g[2*j2 + 1]);

    // ---- load c ----
    float cr[UNITS];
    if (active){
        const float4* cp = (const float4*)(c + r * 20);
        #pragma unroll
        for (int i = 0; i < 5; i++){
            float4 v = cp[i];
            cr[4*i+0] = v.x; cr[4*i+1] = v.y; cr[4*i+2] = v.z; cr[4*i+3] = v.w;
        }
    } else {
        #pragma unroll
        for (int i = 0; i < UNITS; i++) cr[i] = 0.0f;
    }

    // ---- LSTM cell update ----
    float cn[UNITS], hl[UNITS];
    #pragma unroll
    for (int u = 0; u < UNITS; u++){
        float iv = fsigmoid(g[u]);
        float fv = fsigmoid(g[20 + u]);
        float gv = ftanh(g[40 + u]);
        float ov = fsigmoid(g[60 + u]);
        float cnext = fmaf(fv, cr[u], iv * gv);
        cn[u] = cnext;
        hl[u] = ov * ftanh(cnext);
    }

    // ---- lateral: h_next = tanh(h_lstm @ W_lat^T), wl_s pre-transposed ----
    ull lacc[10];
    #pragma unroll
    for (int u2 = 0; u2 < 10; u2++) lacc[u2] = 0ULL;   // two packed +0.0f
    const ull* wl2 = (const ull*)wl_s;
    #pragma unroll
    for (int v = 0; v < UNITS; v++){
        ull s = splat2(hl[v]);
        #pragma unroll
        for (int u2 = 0; u2 < 10; u2++) lacc[u2] = fma2(s, wl2[v * 10 + u2], lacc[u2]);
    }
    float hn[UNITS];
    #pragma unroll
    for (int u2 = 0; u2 < 10; u2++){
        float a, b;
        unpack2(lacc[u2], a, b);
        hn[2*u2]     = ftanh(a);
        hn[2*u2 + 1] = ftanh(b);
    }

    // ---- store: out = [h_next (B*20), c_next (B*20)] ----
    if (active){
        float4* ho = (float4*)(out + r * 20);
        float4* co = (float4*)(out + (long)nrows * 20 + r * 20);
        #pragma unroll
        for (int i = 0; i < 5; i++){
            ho[i] = make_float4(hn[4*i], hn[4*i+1], hn[4*i+2], hn[4*i+3]);
            co[i] = make_float4(cn[4*i], cn[4*i+1], cn[4*i+2], cn[4*i+3]);
        }
    }
}

extern "C" void kernel_launch(void* const* d_in, const int* in_sizes, int n_in,
                              void* d_out, int out_size)
{
    const float* x     = (const float*)d_in[0];
    const float* h     = (const float*)d_in[1];
    const float* c     = (const float*)d_in[2];
    const float* W_ih  = (const float*)d_in[3];
    const float* W_hh  = (const float*)d_in[4];
    const float* b_ih  = (const float*)d_in[5];
    const float* b_hh  = (const float*)d_in[6];
    const float* W_lat = (const float*)d_in[7];
    float* out = (float*)d_out;

    int nrows = in_sizes[0] / UNITS;           // 524288
    int blocks = (nrows + TPB - 1) / TPB;      // 4096

    stn_gpe_kernel<<<blocks, TPB>>>(x, h, c, W_ih, W_hh, b_ih, b_hh, W_lat, out, nrows);
}

// round 2
// speedup vs baseline: 1.1216x; 1.1216x over previous
#include <cuda_runtime.h>
#include <cstdint>

#define TPB 128
typedef unsigned long long ull;

// ---- packed f32x2 helpers (FFMA2 only reachable via PTX) ----
__device__ __forceinline__ ull splat2(float x){
    ull r; asm("mov.b64 %0, {%1, %1};" : "=l"(r) : "f"(x)); return r;
}
__device__ __forceinline__ ull fma2(ull a, ull b, ull c){
    ull d; asm("fma.rn.f32x2 %0, %1, %2, %3;" : "=l"(d) : "l"(a), "l"(b), "l"(c)); return d;
}
__device__ __forceinline__ void unpack2(ull p, float &lo, float &hi){
    asm("mov.b64 {%0, %1}, %2;" : "=f"(lo), "=f"(hi) : "l"(p));
}

// ---- fast transcendentals ----
__device__ __forceinline__ float fast_ex2(float x){
    float y; asm("ex2.approx.f32 %0, %1;" : "=f"(y) : "f"(x)); return y;
}
__device__ __forceinline__ float fast_rcp(float x){
    float y; asm("rcp.approx.f32 %0, %1;" : "=f"(y) : "f"(x)); return y;
}
__device__ __forceinline__ float fsigmoid(float x){
    float e = fast_ex2(-1.4426950408889634f * x);
    return fast_rcp(1.0f + e);
}
__device__ __forceinline__ float ftanh(float x){
    float e = fast_ex2(2.8853900817779268f * x);
    float r = fast_rcp(e + 1.0f);
    return fmaf(-2.0f, r, 1.0f);
}

// Layout:
//  w_s[k*80 + p*40 + j'] : k in [0,40) (x then h), p = lane&1 (unit half),
//    j' = gate-within-half: [0,10)=i, [10,20)=f, [20,30)=g, [30,40)=o for units p*10+j'%10
//  b_s[p*40 + j'] : combined bias, same ordering
//  wl_s[v*24 + p*12 + m] : W_lat[p*10+m][v], m<10 (2 pad)
//  in_s[row*42 + k] : row in [0,128), k<20 = x, k>=20 = h
__global__ void __launch_bounds__(TPB, 3)
stn_gpe_kernel(const float* __restrict__ x, const float* __restrict__ h,
               const float* __restrict__ c,
               const float* __restrict__ W_ih, const float* __restrict__ W_hh,
               const float* __restrict__ b_ih, const float* __restrict__ b_hh,
               const float* __restrict__ W_lat,
               float* __restrict__ out, int nrows)
{
    __shared__ __align__(16) float w_s[40 * 80];     // 12800 B
    __shared__ __align__(16) float b_s[80];
    __shared__ __align__(16) float wl_s[20 * 24];    // 1920 B
    __shared__ __align__(16) float in_s[128 * 42];   // 21504 B

    const int tid = threadIdx.x;

    // ---- fill reorganized weights ----
    for (int idx = tid; idx < 3200; idx += TPB){
        int k = idx / 80, cc = idx - k * 80;
        int p = cc / 40, j = cc - p * 40;
        int gate = j / 10, u = p * 10 + (j - gate * 10);
        int wr = gate * 20 + u;
        w_s[idx] = (k < 20) ? W_ih[wr * 20 + k] : W_hh[wr * 20 + (k - 20)];
    }
    if (tid < 80){
        int p = tid / 40, j = tid - p * 40;
        int gate = j / 10, u = p * 10 + (j - gate * 10);
        int wr = gate * 20 + u;
        b_s[tid] = b_ih[wr] + b_hh[wr];
    }
    for (int idx = tid; idx < 480; idx += TPB){
        int v = idx / 24, t = idx - v * 24;
        int p = t / 12, m = t - p * 12;
        wl_s[idx] = (m < 10) ? W_lat[(p * 10 + m) * 20 + v] : 0.0f;
    }

    // ---- stage inputs for 128 rows (coalesced float4 loads) ----
    const long rowbase = (long)blockIdx.x * 128;
    {
        const float4* x4 = (const float4*)(x + rowbase * 20);
        const float4* h4 = (const float4*)(h + rowbase * 20);
        #pragma unroll
        for (int it = 0; it < 5; it++){
            int i4 = tid + it * TPB;              // < 640
            int row = i4 / 5, k4 = (i4 - row * 5) * 4;
            float4 vx = x4[i4];
            float* dx = &in_s[row * 42 + k4];
            dx[0] = vx.x; dx[1] = vx.y; dx[2] = vx.z; dx[3] = vx.w;
            float4 vh = h4[i4];
            float* dh = &in_s[row * 42 + 20 + k4];
            dh[0] = vh.x; dh[1] = vh.y; dh[2] = vh.z; dh[3] = vh.w;
        }
    }
    __syncthreads();

    const int p = tid & 1;
    const int q = tid >> 1;
    const long r0 = rowbase + q;
    const long r1 = rowbase + 64 + q;
    const float* in0 = &in_s[q * 42];
    const float* in1 = &in_s[(q + 64) * 42];

    // ---- gate GEMV: 40 gates (this half) x 2 rows, packed f32x2 ----
    ull acc0[20], acc1[20];
    {
        const ull* b2 = (const ull*)(b_s + p * 40);
        #pragma unroll
        for (int j = 0; j < 20; j++){ acc0[j] = b2[j]; acc1[j] = b2[j]; }
    }
    const char* wbase = (const char*)w_s + p * 160;
    #pragma unroll 2
    for (int k = 0; k < 40; k++){
        ull s0 = splat2(in0[k]);
        ull s1 = splat2(in1[k]);
        const ulonglong2* wk = (const ulonglong2*)(wbase + k * 320);
        #pragma unroll
        for (int m = 0; m < 10; m++){
            ulonglong2 w = wk[m];
            acc0[2*m]   = fma2(s0, w.x, acc0[2*m]);
            acc0[2*m+1] = fma2(s0, w.y, acc0[2*m+1]);
            acc1[2*m]   = fma2(s1, w.x, acc1[2*m]);
            acc1[2*m+1] = fma2(s1, w.y, acc1[2*m+1]);
        }
    }

    const long coff = (long)nrows * 20;
    float hl0[10], hl1[10];

    // ---- row 0: LSTM update, store c_next immediately ----
    {
        float ga[40];
        #pragma unroll
        for (int j = 0; j < 20; j++) unpack2(acc0[j], ga[2*j], ga[2*j+1]);
        const float2* cp = (const float2*)(c + r0 * 20 + p * 10);
        float2* cout = (float2*)(out + coff + r0 * 20 + p * 10);
        #pragma unroll
        for (int m = 0; m < 5; m++){
            float2 cv = cp[m];
            float2 cw;
            {
                int u = 2 * m;
                float iv = fsigmoid(ga[u]);
                float fv = fsigmoid(ga[10 + u]);
                float gv = ftanh(ga[20 + u]);
                float ov = fsigmoid(ga[30 + u]);
                float cn = fmaf(fv, cv.x, iv * gv);
                cw.x = cn; hl0[u] = ov * ftanh(cn);
            }
            {
                int u = 2 * m + 1;
                float iv = fsigmoid(ga[u]);
                float fv = fsigmoid(ga[10 + u]);
                float gv = ftanh(ga[20 + u]);
                float ov = fsigmoid(ga[30 + u]);
                float cn = fmaf(fv, cv.y, iv * gv);
                cw.y = cn; hl0[u] = ov * ftanh(cn);
            }
            cout[m] = cw;
        }
    }
    // ---- row 1 ----
    {
        float ga[40];
        #pragma unroll
        for (int j = 0; j < 20; j++) unpack2(acc1[j], ga[2*j], ga[2*j+1]);
        const float2* cp = (const float2*)(c + r1 * 20 + p * 10);
        float2* cout = (float2*)(out + coff + r1 * 20 + p * 10);
        #pragma unroll
        for (int m = 0; m < 5; m++){
            float2 cv = cp[m];
            float2 cw;
            {
                int u = 2 * m;
                float iv = fsigmoid(ga[u]);
                float fv = fsigmoid(ga[10 + u]);
                float gv = ftanh(ga[20 + u]);
                float ov = fsigmoid(ga[30 + u]);
                float cn = fmaf(fv, cv.x, iv * gv);
                cw.x = cn; hl1[u] = ov * ftanh(cn);
            }
            {
                int u = 2 * m + 1;
                float iv = fsigmoid(ga[u]);
                float fv = fsigmoid(ga[10 + u]);
                float gv = ftanh(ga[20 + u]);
                float ov = fsigmoid(ga[30 + u]);
                float cn = fmaf(fv, cv.y, iv * gv);
                cw.y = cn; hl1[u] = ov * ftanh(cn);
            }
            cout[m] = cw;
        }
    }

    // ---- lateral: h_next = tanh(h_lstm @ W_lat^T), units split across lane pair ----
    ull la0[5], la1[5];
    #pragma unroll
    for (int j = 0; j < 5; j++){ la0[j] = 0ULL; la1[j] = 0ULL; }

    const int v_own_base = p * 10;
    const int v_par_base = 10 - p * 10;
    #pragma unroll
    for (int i = 0; i < 10; i++){
        float own0 = hl0[i], own1 = hl1[i];
        float pa0 = __shfl_xor_sync(0xffffffffu, own0, 1);
        float pa1 = __shfl_xor_sync(0xffffffffu, own1, 1);
        const ulonglong2* wo = (const ulonglong2*)(wl_s + (v_own_base + i) * 24 + p * 12);
        const ulonglong2* wq = (const ulonglong2*)(wl_s + (v_par_base + i) * 24 + p * 12);
        ulonglong2 a = wo[0], b = wo[1], d = wo[2];
        ull so0 = splat2(own0), so1 = splat2(own1);
        la0[0] = fma2(so0, a.x, la0[0]); la1[0] = fma2(so1, a.x, la1[0]);
        la0[1] = fma2(so0, a.y, la0[1]); la1[1] = fma2(so1, a.y, la1[1]);
        la0[2] = fma2(so0, b.x, la0[2]); la1[2] = fma2(so1, b.x, la1[2]);
        la0[3] = fma2(so0, b.y, la0[3]); la1[3] = fma2(so1, b.y, la1[3]);
        la0[4] = fma2(so0, d.x, la0[4]); la1[4] = fma2(so1, d.x, la1[4]);
        ulonglong2 e = wq[0], f = wq[1], g = wq[2];
        ull sp0 = splat2(pa0), sp1 = splat2(pa1);
        la0[0] = fma2(sp0, e.x, la0[0]); la1[0] = fma2(sp1, e.x, la1[0]);
        la0[1] = fma2(sp0, e.y, la0[1]); la1[1] = fma2(sp1, e.y, la1[1]);
        la0[2] = fma2(sp0, f.x, la0[2]); la1[2] = fma2(sp1, f.x, la1[2]);
        la0[3] = fma2(sp0, f.y, la0[3]); la1[3] = fma2(sp1, f.y, la1[3]);
        la0[4] = fma2(sp0, g.x, la0[4]); la1[4] = fma2(sp1, g.x, la1[4]);
    }

    // ---- tanh + store h_next ----
    {
        float2* ho = (float2*)(out + r0 * 20 + p * 10);
        #pragma unroll
        for (int j = 0; j < 5; j++){
            float lo, hi; unpack2(la0[j], lo, hi);
            float2 v; v.x = ftanh(lo); v.y = ftanh(hi);
            ho[j] = v;
        }
    }
    {
        float2* ho = (float2*)(out + r1 * 20 + p * 10);
        #pragma unroll
        for (int j = 0; j < 5; j++){
            float lo, hi; unpack2(la1[j], lo, hi);
            float2 v; v.x = ftanh(lo); v.y = ftanh(hi);
            ho[j] = v;
        }
    }
}

extern "C" void kernel_launch(void* const* d_in, const int* in_sizes, int n_in,
                              void* d_out, int out_size)
{
    const float* x     = (const float*)d_in[0];
    const float* h     = (const float*)d_in[1];
    const float* c     = (const float*)d_in[2];
    const float* W_ih  = (const float*)d_in[3];
    const float* W_hh  = (const float*)d_in[4];
    const float* b_ih  = (const float*)d_in[5];
    const float* b_hh  = (const float*)d_in[6];
    const float* W_lat = (const float*)d_in[7];
    float* out = (float*)d_out;

    int nrows = in_sizes[0] / 20;              // 524288
    int blocks = nrows / 128;                  // 4096 (B divisible by 128)

    stn_gpe_kernel<<<blocks, TPB>>>(x, h, c, W_ih, W_hh, b_ih, b_hh, W_lat, out, nrows);
}